// round 2
// baseline (speedup 1.0000x reference)
#include <cuda_runtime.h>

#define NUM_SEG 512
#define D 64
#define D4 (D / 4)   // 16 float4 chunks per row

// Scratch (no device allocation allowed): per-segment mean (as float4) and inverse denom.
__device__ float4 g_mean[NUM_SEG * D4];
__device__ float  g_inv[NUM_SEG];

__device__ __forceinline__ int lower_bound_i32(const int* __restrict__ a, int n, int v) {
    int lo = 0, hi = n;
    while (lo < hi) {
        int mid = (lo + hi) >> 1;
        if (a[mid] < v) lo = mid + 1; else hi = mid;
    }
    return lo;
}

// Pass 1: one block per segment. Compute column sums, sum of squared norms, count.
// Rows of a segment are contiguous because batch is sorted.
__global__ __launch_bounds__(256) void pairnorm_stats(
    const float4* __restrict__ x4,   // [N, 16] float4 view of [N, 64]
    const int* __restrict__ batch,   // [N], sorted int32
    int N)
{
    const int s   = blockIdx.x;
    const int tid = threadIdx.x;

    __shared__ int s_lo, s_hi;
    if (tid == 0) s_lo = lower_bound_i32(batch, N, s);
    if (tid == 1) s_hi = lower_bound_i32(batch, N, s + 1);
    __syncthreads();
    const int lo = s_lo, hi = s_hi;
    const int cnt = hi - lo;

    const int c4   = tid & 15;   // which float4 chunk of the row
    const int rgrp = tid >> 4;   // 0..15, row stride group

    float4 sum4 = make_float4(0.f, 0.f, 0.f, 0.f);
    float  sq   = 0.f;
    for (int r = lo + rgrp; r < hi; r += 16) {
        float4 v = x4[(size_t)r * D4 + c4];
        sum4.x += v.x; sum4.y += v.y; sum4.z += v.z; sum4.w += v.w;
        sq += v.x * v.x + v.y * v.y + v.z * v.z + v.w * v.w;
    }

    __shared__ float4 ssum[256];
    __shared__ float  ssq[256];
    __shared__ float  smsq[16];
    ssum[tid] = sum4;
    ssq[tid]  = sq;
    __syncthreads();

    // Reduce across the 16 row groups (same c4 -> tid stride 16)
    for (int off = 128; off >= 16; off >>= 1) {
        if (tid < off) {
            float4 a = ssum[tid], b = ssum[tid + off];
            a.x += b.x; a.y += b.y; a.z += b.z; a.w += b.w;
            ssum[tid] = a;
            ssq[tid] += ssq[tid + off];
        }
        __syncthreads();
    }

    const float invc = 1.f / (float)max(cnt, 1);
    if (tid < 16) {
        float4 t = ssum[tid];
        float4 m = make_float4(t.x * invc, t.y * invc, t.z * invc, t.w * invc);
        g_mean[s * D4 + tid] = m;
        smsq[tid] = m.x * m.x + m.y * m.y + m.z * m.z + m.w * m.w;
    }
    __syncthreads();

    if (tid == 0) {
        float sq_tot = 0.f, msq = 0.f;
#pragma unroll
        for (int i = 0; i < 16; i++) { sq_tot += ssq[i]; msq += smsq[i]; }
        // segment_mean(|x - m|^2) = segment_mean(|x|^2) - |m|^2
        float var = sq_tot * invc - msq;
        g_inv[s] = rsqrtf(var);
    }
}

// Pass 2: out = (x - mean[seg]) * inv_denom[seg], fully vectorized float4 map.
__global__ __launch_bounds__(256) void pairnorm_apply(
    const float4* __restrict__ x4,
    const int* __restrict__ batch,
    float4* __restrict__ out4,
    int total4) // N * 16
{
    int idx = blockIdx.x * blockDim.x + threadIdx.x;
    if (idx >= total4) return;
    const int row = idx >> 4;
    const int c4  = idx & 15;
    int s = batch[row];
    s = min(max(s, 0), NUM_SEG - 1);   // defensive clamp: never OOB on tables

    float4 v = x4[idx];
    float4 m = g_mean[s * D4 + c4];
    float  inv = g_inv[s];
    float4 o;
    o.x = (v.x - m.x) * inv;
    o.y = (v.y - m.y) * inv;
    o.z = (v.z - m.z) * inv;
    o.w = (v.w - m.w) * inv;
    out4[idx] = o;
}

extern "C" void kernel_launch(void* const* d_in, const int* in_sizes, int n_in,
                              void* d_out, int out_size)
{
    const float* x     = (const float*)d_in[0];   // [N, 64]
    const int*   batch = (const int*)d_in[1];     // [N], sorted (int32: JAX x64 demotion)
    float*       out   = (float*)d_out;

    const int N = in_sizes[1];

    const float4* x4   = (const float4*)x;
    float4*       out4 = (float4*)out;

    pairnorm_stats<<<NUM_SEG, 256>>>(x4, batch, N);

    const int total4 = N * D4;
    const int threads = 256;
    const int blocks = (total4 + threads - 1) / threads;
    pairnorm_apply<<<blocks, threads>>>(x4, batch, out4, total4);
}

// round 3
// speedup vs baseline: 1.0918x; 1.0918x over previous
#include <cuda_runtime.h>

#define NUM_SEG 512
#define D 64
#define D4 (D / 4)   // 16 float4 chunks per row
#define TPB 1024
#define RGRPS (TPB / D4)   // 64 row groups

__device__ __forceinline__ int lower_bound_i32(const int* __restrict__ a, int n, int v) {
    int lo = 0, hi = n;
    while (lo < hi) {
        int mid = (lo + hi) >> 1;
        if (a[mid] < v) lo = mid + 1; else hi = mid;
    }
    return lo;
}

// Fused PairNorm: one block per segment (batch sorted -> contiguous row range).
// Phase A reads the segment (lands in L2: <=148 concurrent blocks * ~500KB = 74MB < 126MB L2),
// computes column sums + sum of squared norms. Phase B re-reads (L2 hits) and writes output
// with streaming stores so output lines don't evict resident inputs.
__global__ __launch_bounds__(TPB, 1) void pairnorm_fused(
    const float4* __restrict__ x4,   // [N, 16] float4 view of [N, 64]
    const int* __restrict__ batch,   // [N], sorted int32
    float4* __restrict__ out4,
    int N)
{
    const int s   = blockIdx.x;
    const int tid = threadIdx.x;

    __shared__ int sh_lo, sh_hi;
    if (tid == 0) sh_lo = lower_bound_i32(batch, N, s);
    if (tid == 1) sh_hi = lower_bound_i32(batch, N, s + 1);
    __syncthreads();
    const int lo = sh_lo, hi = sh_hi;
    const int cnt = hi - lo;

    const int c4   = tid & (D4 - 1);   // column chunk 0..15
    const int rgrp = tid >> 4;         // row group 0..63

    // ---- Phase A: accumulate (unroll 2 for MLP) ----
    float4 sum4 = make_float4(0.f, 0.f, 0.f, 0.f);
    float  sq   = 0.f;
    int r = lo + rgrp;
    for (; r + RGRPS < hi; r += 2 * RGRPS) {
        float4 v0 = __ldcg(&x4[(size_t)r * D4 + c4]);
        float4 v1 = __ldcg(&x4[(size_t)(r + RGRPS) * D4 + c4]);
        sum4.x += v0.x + v1.x; sum4.y += v0.y + v1.y;
        sum4.z += v0.z + v1.z; sum4.w += v0.w + v1.w;
        sq += v0.x * v0.x + v0.y * v0.y + v0.z * v0.z + v0.w * v0.w;
        sq += v1.x * v1.x + v1.y * v1.y + v1.z * v1.z + v1.w * v1.w;
    }
    if (r < hi) {
        float4 v0 = __ldcg(&x4[(size_t)r * D4 + c4]);
        sum4.x += v0.x; sum4.y += v0.y; sum4.z += v0.z; sum4.w += v0.w;
        sq += v0.x * v0.x + v0.y * v0.y + v0.z * v0.z + v0.w * v0.w;
    }

    // ---- Block reduction across the 64 row groups ----
    __shared__ float4 ssum[TPB];
    __shared__ float  ssq[TPB];
    __shared__ float4 smean[D4];
    __shared__ float  smsq[D4];
    __shared__ float  sh_inv;

    ssum[tid] = sum4;
    ssq[tid]  = sq;
    __syncthreads();

    for (int off = TPB / 2; off >= D4; off >>= 1) {
        if (tid < off) {
            float4 a = ssum[tid], b = ssum[tid + off];
            a.x += b.x; a.y += b.y; a.z += b.z; a.w += b.w;
            ssum[tid] = a;
            ssq[tid] += ssq[tid + off];
        }
        __syncthreads();
    }

    const float invc = 1.f / (float)max(cnt, 1);
    if (tid < D4) {
        float4 t = ssum[tid];
        float4 m = make_float4(t.x * invc, t.y * invc, t.z * invc, t.w * invc);
        smean[tid] = m;
        smsq[tid]  = m.x * m.x + m.y * m.y + m.z * m.z + m.w * m.w;
    }
    __syncthreads();
    if (tid == 0) {
        float sq_tot = 0.f, msq = 0.f;
#pragma unroll
        for (int i = 0; i < D4; i++) { sq_tot += ssq[i]; msq += smsq[i]; }
        // segment_mean(|x - m|^2) = segment_mean(|x|^2) - |m|^2
        float var = sq_tot * invc - msq;
        sh_inv = rsqrtf(var);
    }
    __syncthreads();

    // ---- Phase B: apply (re-read hits L2; streaming stores/loads) ----
    const float4 m  = smean[c4];
    const float inv = sh_inv;

    r = lo + rgrp;
    for (; r + RGRPS < hi; r += 2 * RGRPS) {
        const size_t i0 = (size_t)r * D4 + c4;
        const size_t i1 = (size_t)(r + RGRPS) * D4 + c4;
        float4 v0 = __ldcs(&x4[i0]);
        float4 v1 = __ldcs(&x4[i1]);
        float4 o0, o1;
        o0.x = (v0.x - m.x) * inv; o0.y = (v0.y - m.y) * inv;
        o0.z = (v0.z - m.z) * inv; o0.w = (v0.w - m.w) * inv;
        o1.x = (v1.x - m.x) * inv; o1.y = (v1.y - m.y) * inv;
        o1.z = (v1.z - m.z) * inv; o1.w = (v1.w - m.w) * inv;
        __stcs(&out4[i0], o0);
        __stcs(&out4[i1], o1);
    }
    if (r < hi) {
        const size_t i0 = (size_t)r * D4 + c4;
        float4 v0 = __ldcs(&x4[i0]);
        float4 o0;
        o0.x = (v0.x - m.x) * inv; o0.y = (v0.y - m.y) * inv;
        o0.z = (v0.z - m.z) * inv; o0.w = (v0.w - m.w) * inv;
        __stcs(&out4[i0], o0);
    }
}

extern "C" void kernel_launch(void* const* d_in, const int* in_sizes, int n_in,
                              void* d_out, int out_size)
{
    const float* x     = (const float*)d_in[0];   // [N, 64]
    const int*   batch = (const int*)d_in[1];     // [N], sorted int32
    float*       out   = (float*)d_out;

    const int N = in_sizes[1];

    pairnorm_fused<<<NUM_SEG, TPB>>>((const float4*)x, batch, (float4*)out, N);
}